// round 2
// baseline (speedup 1.0000x reference)
#include <cuda_runtime.h>

// OptimizedSeriesDecomp: x[32,4096,512] fp32
//   trend = mean_{k in {7,25,49}} boxfilter_k(x, replicate pad) along L
//   out   = concat(residual = x - trend, trend)
//
// Streaming design: one thread per channel column, batches of 8 time rows,
// 57-deep register delay line. Each input element is loaded from DRAM exactly
// once (plus segment warmup halo); the 7x temporal reuse of the naive scheme
// happens entirely in registers, so neither L1 nor L2 capacity matters.
// Pure DRAM-bound: ~824 MB total traffic.

#define BB   32
#define LL   4096
#define CC   512
#define SEG  256
#define NSEG (LL / SEG)      // 16
#define HIST 57              // rows t-24 .. t+32 relative to current output t

__global__ __launch_bounds__(256, 2)
void series_decomp_kernel(const float* __restrict__ x,
                          float* __restrict__ out,
                          long long nhalf)   // elements per output tensor
{
    const int tid  = threadIdx.x;
    const int cblk = blockIdx.x;          // 0..1  (channel half)
    const int seg  = blockIdx.y;          // 0..NSEG-1
    const int b    = blockIdx.z;          // 0..BB-1
    const int c    = cblk * 256 + tid;    // channel 0..511

    const float* __restrict__ xp = x + (long long)b * LL * CC + c;
    float* __restrict__ rp = out +          (long long)b * LL * CC + c;
    float* __restrict__ tp = out + nhalf + (long long)b * LL * CC + c;

    const int t0 = seg * SEG;

    // ---- warmup: fill history h[j] = x[clamp(t0 - 24 + j)], j = 0..56 ----
    float h[HIST];
    #pragma unroll
    for (int j = 0; j < HIST; ++j) {
        int t = t0 - 24 + j;
        t = t < 0 ? 0 : (t > LL - 1 ? LL - 1 : t);
        h[j] = __ldg(xp + (long long)t * CC);
    }

    float s7 = 0.f, s25 = 0.f, s49 = 0.f;
    #pragma unroll
    for (int j = 0;  j < 49; ++j) s49 += h[j];      // rows t0-24 .. t0+24
    #pragma unroll
    for (int j = 12; j < 37; ++j) s25 += h[j];      // rows t0-12 .. t0+12
    #pragma unroll
    for (int j = 21; j < 28; ++j) s7  += h[j];      // rows t0-3  .. t0+3

    const float w7  = 1.0f / (7.0f  * 3.0f);
    const float w25 = 1.0f / (25.0f * 3.0f);
    const float w49 = 1.0f / (49.0f * 3.0f);

    // ---- main loop: 8 outputs per iteration ----
    #pragma unroll 1
    for (int tb = t0; tb < t0 + SEG; tb += 8) {
        // Prefetch the next 8 rows (tb+33 .. tb+40) a full body early.
        float nxt[8];
        #pragma unroll
        for (int j = 0; j < 8; ++j) {
            int t = tb + 33 + j;
            t = t > LL - 1 ? LL - 1 : t;
            nxt[j] = __ldg(xp + (long long)t * CC);
        }

        // Invariant: h[j] = x[clamp(tb - 24 + j)], windows centered at tb.
        #pragma unroll
        for (int i = 0; i < 8; ++i) {
            float tr = s7 * w7 + s25 * w25 + s49 * w49;
            float xc = h[24 + i];
            long long o = (long long)(tb + i) * CC;
            rp[o] = xc - tr;
            tp[o] = tr;
            // slide all three windows one row forward
            s7  += h[28 + i] - h[21 + i];
            s25 += h[37 + i] - h[12 + i];
            s49 += h[49 + i] - h[i];
        }

        // shift history by 8 and append the prefetched rows
        #pragma unroll
        for (int j = 0; j < HIST - 8; ++j) h[j] = h[j + 8];
        #pragma unroll
        for (int j = 0; j < 8; ++j) h[HIST - 8 + j] = nxt[j];
    }
}

extern "C" void kernel_launch(void* const* d_in, const int* in_sizes, int n_in,
                              void* d_out, int out_size)
{
    const float* x = (const float*)d_in[0];
    float* out = (float*)d_out;
    long long nhalf = (long long)out_size / 2;   // residual | trend

    dim3 grid(CC / 256, NSEG, BB);   // (2, 16, 32) = 1024 blocks
    series_decomp_kernel<<<grid, 256>>>(x, out, nhalf);
}

// round 6
// speedup vs baseline: 1.1848x; 1.1848x over previous
#include <cuda_runtime.h>

// OptimizedSeriesDecomp: x[32,4096,512] fp32
//   trend = mean_{k in {7,25,49}} boxfilter_k(x, replicate pad) along L
//   out   = concat(residual = x - trend, trend)
//
// R6 == R3/R4/R5 (never benched; repeated GPU acquisition failures):
// streaming register-delay-line kernel, batch 16 rows to double in-flight LDG
// bytes per warp (R2 profile: 63% DRAM, latency-bound). History covers rows
// t-24..t+40 (HIST=65); prefetch fills tb+41..tb+56 one full body ahead.
// Streaming stores for write-once outputs.

#define BB    32
#define LL    4096
#define CC    512
#define SEG   256
#define NSEG  (LL / SEG)      // 16
#define BATCH 16
#define HIST  (49 + BATCH)    // 65

__global__ __launch_bounds__(256, 2)
void series_decomp_kernel(const float* __restrict__ x,
                          float* __restrict__ out,
                          long long nhalf)   // elements per output tensor
{
    const int tid  = threadIdx.x;
    const int cblk = blockIdx.x;          // 0..1  (channel half)
    const int seg  = blockIdx.y;          // 0..NSEG-1
    const int b    = blockIdx.z;          // 0..BB-1
    const int c    = cblk * 256 + tid;    // channel 0..511

    const float* __restrict__ xp = x + (long long)b * LL * CC + c;
    float* __restrict__ rp = out +          (long long)b * LL * CC + c;
    float* __restrict__ tp = out + nhalf + (long long)b * LL * CC + c;

    const int t0 = seg * SEG;

    // ---- warmup: h[j] = x[clamp(t0 - 24 + j)], j = 0..HIST-1 ----
    float h[HIST];
    #pragma unroll
    for (int j = 0; j < HIST; ++j) {
        int t = t0 - 24 + j;
        t = t < 0 ? 0 : (t > LL - 1 ? LL - 1 : t);
        h[j] = __ldg(xp + (long long)t * CC);
    }

    float s7 = 0.f, s25 = 0.f, s49 = 0.f;
    #pragma unroll
    for (int j = 0;  j < 49; ++j) s49 += h[j];      // rows t0-24 .. t0+24
    #pragma unroll
    for (int j = 12; j < 37; ++j) s25 += h[j];      // rows t0-12 .. t0+12
    #pragma unroll
    for (int j = 21; j < 28; ++j) s7  += h[j];      // rows t0-3  .. t0+3

    const float w7  = 1.0f / (7.0f  * 3.0f);
    const float w25 = 1.0f / (25.0f * 3.0f);
    const float w49 = 1.0f / (49.0f * 3.0f);

    // ---- main loop: BATCH outputs per iteration ----
    #pragma unroll 1
    for (int tb = t0; tb < t0 + SEG; tb += BATCH) {
        // Prefetch the next BATCH rows (tb+41 .. tb+40+BATCH), one body early.
        float nxt[BATCH];
        #pragma unroll
        for (int j = 0; j < BATCH; ++j) {
            int t = tb + (HIST - 24) + j;          // tb + 41 + j
            t = t > LL - 1 ? LL - 1 : t;
            nxt[j] = __ldg(xp + (long long)t * CC);
        }

        // Invariant: h[j] = x[clamp(tb - 24 + j)], windows centered at tb.
        #pragma unroll
        for (int i = 0; i < BATCH; ++i) {
            float tr = s7 * w7 + s25 * w25 + s49 * w49;
            float xc = h[24 + i];
            long long o = (long long)(tb + i) * CC;
            __stcs(rp + o, xc - tr);
            __stcs(tp + o, tr);
            // slide all three windows one row forward
            s7  += h[28 + i] - h[21 + i];
            s25 += h[37 + i] - h[12 + i];
            s49 += h[49 + i] - h[i];
        }

        // shift history by BATCH and append the prefetched rows
        #pragma unroll
        for (int j = 0; j < HIST - BATCH; ++j) h[j] = h[j + BATCH];
        #pragma unroll
        for (int j = 0; j < BATCH; ++j) h[HIST - BATCH + j] = nxt[j];
    }
}

extern "C" void kernel_launch(void* const* d_in, const int* in_sizes, int n_in,
                              void* d_out, int out_size)
{
    const float* x = (const float*)d_in[0];
    float* out = (float*)d_out;
    long long nhalf = (long long)out_size / 2;   // residual | trend

    dim3 grid(CC / 256, NSEG, BB);   // (2, 16, 32) = 1024 blocks
    series_decomp_kernel<<<grid, 256>>>(x, out, nhalf);
}

// round 7
// speedup vs baseline: 1.2402x; 1.0468x over previous
#include <cuda_runtime.h>

// OptimizedSeriesDecomp: x[32,4096,512] fp32
//   trend = mean_{k in {7,25,49}} boxfilter_k(x, replicate pad) along L
//   out   = concat(residual = x - trend, trend)
//
// R7: persistent balanced partition. 592 blocks (=4/SM x 148) of 128 threads;
// each block owns a contiguous run of ~885 rows in flattened (strip,time)
// space (16-row units). Kills the 4-wave quantization (86.5% ceiling in R6)
// and amortizes the 49-row warmup halo over ~885-row runs (read amp
// 1.25x -> 1.07x). Same register delay line (HIST=65, BATCH=16), __stcs.

#define BB    32
#define LL    4096
#define CC    512
#define TPB   128                      // threads per block
#define CGRP  (CC / TPB)               // 4 channel groups
#define NSTRIP (BB * CGRP)             // 128 strips
#define NBLOCK 592                     // 4 per SM * 148 SMs
#define BATCH 16
#define HIST  (49 + BATCH)             // 65
#define UNITS_PER_STRIP (LL / BATCH)   // 256 (16-row units)
#define TOTAL_UNITS (NSTRIP * UNITS_PER_STRIP)  // 32768

__global__ __launch_bounds__(TPB, 4)
void series_decomp_kernel(const float* __restrict__ x,
                          float* __restrict__ out,
                          long long nhalf)   // elements per output tensor
{
    const int tid = threadIdx.x;
    const int blk = blockIdx.x;

    // Balanced carve of 16-row units: block i owns [u0, u1).
    int u0 = (int)(((long long)blk       * TOTAL_UNITS) / NBLOCK);
    int u1 = (int)(((long long)(blk + 1) * TOTAL_UNITS) / NBLOCK);

    const float w7  = 1.0f / (7.0f  * 3.0f);
    const float w25 = 1.0f / (25.0f * 3.0f);
    const float w49 = 1.0f / (49.0f * 3.0f);

    // A run crosses at most one strip boundary -> at most 2 iterations.
    while (u0 < u1) {
        const int strip = u0 / UNITS_PER_STRIP;
        const int su    = u0 % UNITS_PER_STRIP;
        const int len_u = min(UNITS_PER_STRIP - su, u1 - u0);
        const int t0    = su * BATCH;
        const int tend  = t0 + len_u * BATCH;

        const int b = strip / CGRP;
        const int g = strip % CGRP;
        const int c = g * TPB + tid;

        const float* __restrict__ xp = x + (long long)b * LL * CC + c;
        float* __restrict__ rp = out +          (long long)b * LL * CC + c;
        float* __restrict__ tp = out + nhalf + (long long)b * LL * CC + c;

        // ---- warmup: h[j] = x[clamp(t0 - 24 + j)], j = 0..HIST-1 ----
        float h[HIST];
        #pragma unroll
        for (int j = 0; j < HIST; ++j) {
            int t = t0 - 24 + j;
            t = t < 0 ? 0 : (t > LL - 1 ? LL - 1 : t);
            h[j] = __ldg(xp + (long long)t * CC);
        }

        float s7 = 0.f, s25 = 0.f, s49 = 0.f;
        #pragma unroll
        for (int j = 0;  j < 49; ++j) s49 += h[j];   // rows t0-24 .. t0+24
        #pragma unroll
        for (int j = 12; j < 37; ++j) s25 += h[j];   // rows t0-12 .. t0+12
        #pragma unroll
        for (int j = 21; j < 28; ++j) s7  += h[j];   // rows t0-3  .. t0+3

        // ---- main loop: BATCH outputs per iteration ----
        #pragma unroll 1
        for (int tb = t0; tb < tend; tb += BATCH) {
            // Prefetch the next BATCH rows (tb+41 .. tb+56), one body early.
            float nxt[BATCH];
            #pragma unroll
            for (int j = 0; j < BATCH; ++j) {
                int t = tb + (HIST - 24) + j;        // tb + 41 + j
                t = t > LL - 1 ? LL - 1 : t;
                nxt[j] = __ldg(xp + (long long)t * CC);
            }

            // Invariant: h[j] = x[clamp(tb - 24 + j)], windows centered at tb.
            #pragma unroll
            for (int i = 0; i < BATCH; ++i) {
                float tr = s7 * w7 + s25 * w25 + s49 * w49;
                float xc = h[24 + i];
                long long o = (long long)(tb + i) * CC;
                __stcs(rp + o, xc - tr);
                __stcs(tp + o, tr);
                // slide all three windows one row forward
                s7  += h[28 + i] - h[21 + i];
                s25 += h[37 + i] - h[12 + i];
                s49 += h[49 + i] - h[i];
            }

            // shift history by BATCH and append the prefetched rows
            #pragma unroll
            for (int j = 0; j < HIST - BATCH; ++j) h[j] = h[j + BATCH];
            #pragma unroll
            for (int j = 0; j < BATCH; ++j) h[HIST - BATCH + j] = nxt[j];
        }

        u0 += len_u;
    }
}

extern "C" void kernel_launch(void* const* d_in, const int* in_sizes, int n_in,
                              void* d_out, int out_size)
{
    const float* x = (const float*)d_in[0];
    float* out = (float*)d_out;
    long long nhalf = (long long)out_size / 2;   // residual | trend

    series_decomp_kernel<<<NBLOCK, TPB>>>(x, out, nhalf);
}

// round 11
// speedup vs baseline: 1.2969x; 1.0457x over previous
#include <cuda_runtime.h>
#include <cstdint>

// OptimizedSeriesDecomp: x[32,4096,512] fp32
//   trend = mean_{k in {7,25,49}} boxfilter_k(x, replicate pad) along L
//   out   = concat(residual = x - trend, trend)
//
// R11 == R8/R9/R10 (never benched: repeated GPU acquisition failures).
// Kill per-thread STG issue cost (512 STG.32 x 5cyc ~= 75% of the LSU round
// budget == the 74% DRAM ceiling measured in R6/R7). 512-thread blocks own
// all channels of a row range -> each 16-row output tile is contiguous 32KB.
// Outputs staged in SMEM (conflict-free STS.32) and drained with
// cp.async.bulk smem->gmem (TMA path, no per-thread stores), double-buffered.
// Register delay line (HIST=65, BATCH=16) unchanged; prefetch a full body
// ahead. Persistent balanced carve (148 blocks, 1/SM).

#define BB     32
#define LL     4096
#define CC     512
#define TPB    512
#define BATCH  16
#define HIST   (49 + BATCH)            // 65
#define NBLOCK 148
#define UPS    (LL / BATCH)            // 256 units per strip
#define TOTAL_UNITS (BB * UPS)         // 8192
#define TILE   (BATCH * CC)            // 8192 floats = 32KB per stream tile
#define SMEM_BYTES (4 * TILE * 4)      // 2 bufs x 2 streams x 32KB = 128KB

__device__ __forceinline__ uint32_t smem_u32(const void* p) {
    uint32_t a;
    asm("{ .reg .u64 t; cvta.to.shared.u64 t, %1; cvt.u32.u64 %0, t; }"
        : "=r"(a) : "l"(p));
    return a;
}
__device__ __forceinline__ void bulk_s2g(void* g, uint32_t s, uint32_t nbytes) {
    asm volatile("cp.async.bulk.global.shared::cta.bulk_group [%0], [%1], %2;"
                 :: "l"(g), "r"(s), "r"(nbytes) : "memory");
}

__global__ __launch_bounds__(TPB, 1)
void series_decomp_kernel(const float* __restrict__ x,
                          float* __restrict__ out,
                          long long nhalf)
{
    extern __shared__ float stage[];   // [2 bufs][2 streams][TILE]
    const int tid = threadIdx.x;
    const uint32_t stage_base = smem_u32(stage);

    int u0 = (int)(((long long)blockIdx.x       * TOTAL_UNITS) / NBLOCK);
    int u1 = (int)(((long long)(blockIdx.x + 1) * TOTAL_UNITS) / NBLOCK);

    const float w7  = 1.0f / (7.0f  * 3.0f);
    const float w25 = 1.0f / (25.0f * 3.0f);
    const float w49 = 1.0f / (49.0f * 3.0f);

    int buf = 0;

    while (u0 < u1) {
        const int b    = u0 / UPS;
        const int su   = u0 % UPS;
        const int len  = min(UPS - su, u1 - u0);
        const int t0   = su * BATCH;
        const int tend = t0 + len * BATCH;

        const float* __restrict__ xp = x + (size_t)b * (LL * CC) + tid;

        // ---- warmup: h[j] = x[clamp(t0 - 24 + j)], j = 0..64 ----
        float h[HIST];
        #pragma unroll
        for (int j = 0; j < HIST; ++j) {
            int t = t0 - 24 + j;
            t = t < 0 ? 0 : (t > LL - 1 ? LL - 1 : t);
            h[j] = __ldg(xp + (size_t)t * CC);
        }
        float s7 = 0.f, s25 = 0.f, s49 = 0.f;
        #pragma unroll
        for (int j = 0;  j < 49; ++j) s49 += h[j];
        #pragma unroll
        for (int j = 12; j < 37; ++j) s25 += h[j];
        #pragma unroll
        for (int j = 21; j < 28; ++j) s7  += h[j];

        // first prefetch: rows t0+41 .. t0+56 (consumed at end of body 1)
        float nxt[BATCH];
        #pragma unroll
        for (int j = 0; j < BATCH; ++j) {
            int t = t0 + 41 + j;
            t = t > LL - 1 ? LL - 1 : t;
            nxt[j] = __ldg(xp + (size_t)t * CC);
        }

        #pragma unroll 1
        for (int tb = t0; tb < tend; tb += BATCH) {
            // gate reuse of stage[buf]: group issued 2 bodies ago must be read
            if (tid == 0)
                asm volatile("cp.async.bulk.wait_group.read 1;" ::: "memory");
            __syncthreads();

            float* __restrict__ sr = stage + (buf * 2 + 0) * TILE;
            float* __restrict__ st = stage + (buf * 2 + 1) * TILE;

            // compute 16 rows; STS conflict-free (contiguous per warp)
            #pragma unroll
            for (int i = 0; i < BATCH; ++i) {
                float tr = s7 * w7 + s25 * w25 + s49 * w49;
                float xc = h[24 + i];
                sr[i * CC + tid] = xc - tr;
                st[i * CC + tid] = tr;
                s7  += h[28 + i] - h[21 + i];
                s25 += h[37 + i] - h[12 + i];
                s49 += h[49 + i] - h[i];
            }

            // shift: consume prefetch issued ONE FULL BODY ago
            #pragma unroll
            for (int j = 0; j < HIST - BATCH; ++j) h[j] = h[j + BATCH];
            #pragma unroll
            for (int j = 0; j < BATCH; ++j) h[HIST - BATCH + j] = nxt[j];

            // issue next prefetch: rows tb+57 .. tb+72 (for next body)
            #pragma unroll
            for (int j = 0; j < BATCH; ++j) {
                int t = tb + BATCH + 41 + j;
                t = t > LL - 1 ? LL - 1 : t;
                nxt[j] = __ldg(xp + (size_t)t * CC);
            }

            // make STS visible to the async proxy, then drain via bulk copy
            asm volatile("fence.proxy.async.shared::cta;" ::: "memory");
            __syncthreads();
            if (tid == 0) {
                size_t o = ((size_t)b * LL + tb) * CC;
                bulk_s2g(out + o,
                         stage_base + (uint32_t)((buf * 2 + 0) * TILE * 4),
                         (uint32_t)(TILE * 4));
                bulk_s2g(out + nhalf + o,
                         stage_base + (uint32_t)((buf * 2 + 1) * TILE * 4),
                         (uint32_t)(TILE * 4));
                asm volatile("cp.async.bulk.commit_group;" ::: "memory");
            }
            buf ^= 1;
        }
        u0 += len;
    }

    // drain all pending bulk reads before smem is deallocated
    if (tid == 0)
        asm volatile("cp.async.bulk.wait_group.read 0;" ::: "memory");
    __syncthreads();
}

extern "C" void kernel_launch(void* const* d_in, const int* in_sizes, int n_in,
                              void* d_out, int out_size)
{
    const float* x = (const float*)d_in[0];
    float* out = (float*)d_out;
    long long nhalf = (long long)out_size / 2;   // residual | trend

    cudaFuncSetAttribute(series_decomp_kernel,
                         cudaFuncAttributeMaxDynamicSharedMemorySize, SMEM_BYTES);
    series_decomp_kernel<<<NBLOCK, TPB, SMEM_BYTES>>>(x, out, nhalf);
}